// round 1
// baseline (speedup 1.0000x reference)
#include <cuda_runtime.h>
#include <cuda_fp16.h>
#include <mma.h>

using namespace nvcuda;

#define N_CELLS 8192
#define D_GENE  1024
#define D_EMB   256
#define KCAT    768   // [hi | lo | hi] split concat along K

// ---------------- scratch (device globals; no allocation allowed) ----------------
__device__ __half g_Bcat[(size_t)N_CELLS * KCAT];   // [Eh | Eh | El]   12.6 MB
__device__ __half g_Acat[(size_t)N_CELLS * KCAT];   // [Ph | Pl | Ph]   12.6 MB
__device__ __half g_B2[(size_t)KCAT * D_EMB];       // [Th ; Tl ; Th]    0.4 MB
__device__ __half g_Xh[(size_t)N_CELLS * D_GENE];   // expression fp16  16 MB
__device__ __half g_Gh[(size_t)D_GENE * D_GENE];    // gene_response    2 MB
__device__ __half g_gated[(size_t)N_CELLS * N_CELLS]; // gated matrix  128 MB
__device__ __half g_M1h[(size_t)N_CELLS * D_GENE];  // (gated@expr)     16 MB

// ---------------- conversion kernels ----------------
__global__ void k_cvt_expr(const float* __restrict__ in) {
    int i = blockIdx.x * blockDim.x + threadIdx.x;
    if (i < N_CELLS * D_GENE) g_Xh[i] = __float2half_rn(in[i]);
}

__global__ void k_cvt_gr(const float* __restrict__ in) {
    int i = blockIdx.x * blockDim.x + threadIdx.x;
    if (i < D_GENE * D_GENE) g_Gh[i] = __float2half_rn(in[i]);
}

// encoding [N, 256] -> Bcat [N, 768] = [Eh | Eh | El]
__global__ void k_cvt_enc(const float* __restrict__ enc) {
    int i = blockIdx.x * blockDim.x + threadIdx.x;
    if (i >= N_CELLS * D_EMB) return;
    int m = i / D_EMB, c = i % D_EMB;
    float x = enc[i];
    __half h = __float2half_rn(x);
    __half l = __float2half_rn(x - __half2float(h));
    size_t base = (size_t)m * KCAT + c;
    g_Bcat[base]             = h;
    g_Bcat[base + D_EMB]     = h;
    g_Bcat[base + 2 * D_EMB] = l;
}

// transform [256, 256] -> B2 [768, 256] = [Th ; Tl ; Th]
__global__ void k_cvt_T(const float* __restrict__ T) {
    int i = blockIdx.x * blockDim.x + threadIdx.x;
    if (i >= D_EMB * D_EMB) return;
    int k = i / D_EMB, j = i % D_EMB;
    float x = T[i];
    __half h = __float2half_rn(x);
    __half l = __float2half_rn(x - __half2float(h));
    g_B2[(size_t)k * D_EMB + j]               = h;
    g_B2[(size_t)(k + D_EMB) * D_EMB + j]     = l;
    g_B2[(size_t)(k + 2 * D_EMB) * D_EMB + j] = h;
}

// ---------------- fused wmma GEMM ----------------
// MODE 0: P = Bcat @ B2         (M=8192, N=256,  K=768)  epi: split-write Acat
// MODE 1: S = Acat @ Bcat^T     (M=8192, N=8192, K=768)  epi: sigmoid * spatial -> gated
// MODE 2: M1 = gated @ Xh       (M=8192, N=1024, K=8192) epi: fp16 -> M1h
// MODE 3: out = M1h @ Gh        (M=8192, N=1024, K=1024) epi: *1/1024 -> out fp32
template <int MODE>
__global__ __launch_bounds__(256, 2)
void gemm_wmma(const float* __restrict__ aux, float* __restrict__ outf) {
    constexpr bool B_COL = (MODE == 1);
    constexpr int K    = (MODE <= 1) ? KCAT : (MODE == 2 ? N_CELLS : D_GENE);
    constexpr int Ndim = (MODE == 0) ? D_EMB : (MODE == 1 ? N_CELLS : D_GENE);

    const __half* __restrict__ A =
        (MODE == 0) ? g_Bcat : (MODE == 1) ? g_Acat : (MODE == 2) ? g_gated : g_M1h;
    const __half* __restrict__ B =
        (MODE == 0) ? g_B2 : (MODE == 1) ? g_Bcat : (MODE == 2) ? g_Xh : g_Gh;

    __shared__ __half As[128 * 40];   // [128 rows][32 k] pad->40
    __shared__ __half Bs[128 * 40];   // col path: [128 n][32 k] pad 40; row path: [32 k][128 n] pad 136
    __shared__ float  epbuf[8][16 * 20];

    const int tid  = threadIdx.x;
    const int w    = tid >> 5;
    const int lane = tid & 31;
    const int wm   = w >> 2;   // 0..1
    const int wn   = w & 3;    // 0..3
    const size_t gm0 = (size_t)blockIdx.y * 128;
    const size_t gn0 = (size_t)blockIdx.x * 128;

    wmma::fragment<wmma::accumulator, 16, 16, 16, float> c[4][2];
#pragma unroll
    for (int i = 0; i < 4; i++)
#pragma unroll
        for (int j = 0; j < 2; j++) wmma::fill_fragment(c[i][j], 0.0f);

    for (int k0 = 0; k0 < K; k0 += 32) {
        // load A tile 128x32 (512 float4, 2 per thread)
#pragma unroll
        for (int t = 0; t < 2; t++) {
            int idx = tid + t * 256;
            int row = idx >> 2, c4 = idx & 3;
            *(float4*)(&As[row * 40 + c4 * 8]) =
                *(const float4*)(A + (gm0 + row) * K + k0 + c4 * 8);
        }
        if (B_COL) {
            // B is [N,K] row-major; tile 128(n) x 32(k)
#pragma unroll
            for (int t = 0; t < 2; t++) {
                int idx = tid + t * 256;
                int row = idx >> 2, c4 = idx & 3;
                *(float4*)(&Bs[row * 40 + c4 * 8]) =
                    *(const float4*)(B + (gn0 + row) * K + k0 + c4 * 8);
            }
        } else {
            // B is [K,N] row-major; tile 32(k) x 128(n)
#pragma unroll
            for (int t = 0; t < 2; t++) {
                int idx = tid + t * 256;
                int row = idx >> 4, c4 = idx & 15;
                *(float4*)(&Bs[row * 136 + c4 * 8]) =
                    *(const float4*)(B + (size_t)(k0 + row) * Ndim + gn0 + c4 * 8);
            }
        }
        __syncthreads();

#pragma unroll
        for (int kk = 0; kk < 32; kk += 16) {
            if constexpr (B_COL) {
                wmma::fragment<wmma::matrix_b, 16, 16, 16, __half, wmma::col_major> b[2];
                wmma::load_matrix_sync(b[0], &Bs[(wn * 32 + 0)  * 40 + kk], 40);
                wmma::load_matrix_sync(b[1], &Bs[(wn * 32 + 16) * 40 + kk], 40);
#pragma unroll
                for (int i = 0; i < 4; i++) {
                    wmma::fragment<wmma::matrix_a, 16, 16, 16, __half, wmma::row_major> a;
                    wmma::load_matrix_sync(a, &As[(wm * 64 + i * 16) * 40 + kk], 40);
                    wmma::mma_sync(c[i][0], a, b[0], c[i][0]);
                    wmma::mma_sync(c[i][1], a, b[1], c[i][1]);
                }
            } else {
                wmma::fragment<wmma::matrix_b, 16, 16, 16, __half, wmma::row_major> b[2];
                wmma::load_matrix_sync(b[0], &Bs[kk * 136 + wn * 32 + 0],  136);
                wmma::load_matrix_sync(b[1], &Bs[kk * 136 + wn * 32 + 16], 136);
#pragma unroll
                for (int i = 0; i < 4; i++) {
                    wmma::fragment<wmma::matrix_a, 16, 16, 16, __half, wmma::row_major> a;
                    wmma::load_matrix_sync(a, &As[(wm * 64 + i * 16) * 40 + kk], 40);
                    wmma::mma_sync(c[i][0], a, b[0], c[i][0]);
                    wmma::mma_sync(c[i][1], a, b[1], c[i][1]);
                }
            }
        }
        __syncthreads();
    }

    // ---------------- epilogue (per-warp, via small shared staging) ----------------
    const int r     = lane >> 1;
    const int cbase = (lane & 1) * 8;
#pragma unroll
    for (int i = 0; i < 4; i++) {
#pragma unroll
        for (int j = 0; j < 2; j++) {
            wmma::store_matrix_sync(&epbuf[w][0], c[i][j], 20, wmma::mem_row_major);
            __syncwarp();
            size_t gr = gm0 + wm * 64 + i * 16 + r;
            size_t gc = gn0 + wn * 32 + j * 16 + cbase;
#pragma unroll
            for (int e = 0; e < 8; e++) {
                float v = epbuf[w][r * 20 + cbase + e];
                size_t col = gc + e;
                if constexpr (MODE == 0) {
                    __half h = __float2half_rn(v);
                    __half l = __float2half_rn(v - __half2float(h));
                    size_t base = gr * KCAT + col;
                    g_Acat[base]             = h;   // Ph
                    g_Acat[base + D_EMB]     = l;   // Pl
                    g_Acat[base + 2 * D_EMB] = h;   // Ph
                } else if constexpr (MODE == 1) {
                    size_t idx = gr * (size_t)N_CELLS + col;
                    float pdv = aux[idx];
                    float sig = 1.0f / (1.0f + __expf(-v));
                    g_gated[idx] = __float2half_rn(sig * __expf(pdv * -1e-4f));
                } else if constexpr (MODE == 2) {
                    g_M1h[gr * D_GENE + col] = __float2half_rn(v);
                } else {
                    outf[gr * D_GENE + col] = v * (1.0f / 1024.0f);
                }
            }
            __syncwarp();
        }
    }
}

// ---------------- launch ----------------
extern "C" void kernel_launch(void* const* d_in, const int* in_sizes, int n_in,
                              void* d_out, int out_size) {
    const float* expr = (const float*)d_in[0];
    const float* enc  = (const float*)d_in[1];
    const float* pd   = (const float*)d_in[2];
    const float* T    = (const float*)d_in[3];
    const float* gr   = (const float*)d_in[4];
    float* out = (float*)d_out;

    k_cvt_expr<<<(N_CELLS * D_GENE) / 256, 256>>>(expr);
    k_cvt_gr<<<(D_GENE * D_GENE) / 256, 256>>>(gr);
    k_cvt_enc<<<(N_CELLS * D_EMB) / 256, 256>>>(enc);
    k_cvt_T<<<(D_EMB * D_EMB) / 256, 256>>>(T);

    // P = enc @ T (fp16 hi/lo split, K=768), split-write into Acat
    gemm_wmma<0><<<dim3(D_EMB / 128, N_CELLS / 128), 256>>>(nullptr, nullptr);
    // scores + sigmoid + spatial gate -> gated (fp16)
    gemm_wmma<1><<<dim3(N_CELLS / 128, N_CELLS / 128), 256>>>(pd, nullptr);
    // M1 = gated @ expression -> fp16
    gemm_wmma<2><<<dim3(D_GENE / 128, N_CELLS / 128), 256>>>(nullptr, nullptr);
    // out = M1 @ gene_response / 1024 -> fp32
    gemm_wmma<3><<<dim3(D_GENE / 128, N_CELLS / 128), 256>>>(nullptr, out);
}